// round 1
// baseline (speedup 1.0000x reference)
#include <cuda_runtime.h>
#include <cuda_bf16.h>

// out[n,c] = 0.05f * sum_{m,t,v} x[n,m,c,t,v]
// (VQ assignments in the reference conserve per-sample totals at every
//  pooling level, so the output is independent of the prototypes.)

#define N_SAMP 32
#define M_DIM  2
#define C_DIM  256
#define TV     6400          // T*V = 256*25
#define TV4    1600          // TV / 4

__global__ __launch_bounds__(256)
void pretrain_neck_reduce(const float* __restrict__ x, float* __restrict__ out) {
    const int bid = blockIdx.x;            // [0, N_SAMP*C_DIM)
    const int n = bid >> 8;                // / 256
    const int c = bid & 255;

    const int tid = threadIdx.x;

    // Two contiguous 6400-float slices: m=0 and m=1.
    const float4* p0 = reinterpret_cast<const float4*>(
        x + ((size_t)(n * M_DIM + 0) * C_DIM + c) * (size_t)TV);
    const float4* p1 = reinterpret_cast<const float4*>(
        x + ((size_t)(n * M_DIM + 1) * C_DIM + c) * (size_t)TV);

    float s0 = 0.f, s1 = 0.f;
    // 1600 float4 per slice, 256 threads -> 6.25 iters; batch loads for MLP.
    #pragma unroll 4
    for (int i = tid; i < TV4; i += 256) {
        float4 a = p0[i];
        float4 b = p1[i];
        s0 += (a.x + a.y) + (a.z + a.w);
        s1 += (b.x + b.y) + (b.z + b.w);
    }
    float s = s0 + s1;

    // warp reduce
    #pragma unroll
    for (int off = 16; off > 0; off >>= 1)
        s += __shfl_down_sync(0xFFFFFFFFu, s, off);

    __shared__ float warp_sums[8];
    const int lane = tid & 31;
    const int wid  = tid >> 5;
    if (lane == 0) warp_sums[wid] = s;
    __syncthreads();

    if (wid == 0) {
        float t = (lane < 8) ? warp_sums[lane] : 0.f;
        #pragma unroll
        for (int off = 4; off > 0; off >>= 1)
            t += __shfl_down_sync(0xFFFFFFFFu, t, off);
        if (lane == 0)
            out[bid] = t * 0.05f;   // (1/M) * (1/Kl) = (1/2)*(1/10)
    }
}

extern "C" void kernel_launch(void* const* d_in, const int* in_sizes, int n_in,
                              void* d_out, int out_size) {
    const float* x = (const float*)d_in[0];   // [N, M, C, T, V] fp32
    float* out = (float*)d_out;               // [N, C] fp32, out_size = 8192
    (void)in_sizes; (void)n_in; (void)out_size;
    pretrain_neck_reduce<<<N_SAMP * C_DIM, 256>>>(x, out);
}

// round 2
// speedup vs baseline: 1.0212x; 1.0212x over previous
#include <cuda_runtime.h>
#include <cuda_bf16.h>

// out[n,c] = 0.05f * sum_{m,t,v} x[n,m,c,t,v]
// (VQ assignments in the reference conserve per-sample totals at every
//  pooling level, so the output is independent of the prototypes.)
//
// R2: 320 threads/block so 1600 float4 per m-slice divides exactly (5 iters),
// fully unrolled branch-free body with 10 independent streaming (__ldcs)
// float4 loads per thread for max MLP; evict-first to stop L2 thrash.

#define N_SAMP 32
#define M_DIM  2
#define C_DIM  256
#define TV     6400          // T*V = 256*25
#define TV4    1600          // TV / 4
#define BT     320           // block threads: 1600 / 320 = 5 exactly

__global__ __launch_bounds__(BT)
void pretrain_neck_reduce(const float* __restrict__ x, float* __restrict__ out) {
    const int bid = blockIdx.x;            // [0, N_SAMP*C_DIM)
    const int n = bid >> 8;
    const int c = bid & 255;

    const int tid = threadIdx.x;

    const float4* p0 = reinterpret_cast<const float4*>(
        x + ((size_t)(n * M_DIM + 0) * C_DIM + c) * (size_t)TV);
    const float4* p1 = reinterpret_cast<const float4*>(
        x + ((size_t)(n * M_DIM + 1) * C_DIM + c) * (size_t)TV);

    // 10 independent streaming loads, fully unrolled — no tail, no predication.
    float4 v[10];
    #pragma unroll
    for (int j = 0; j < 5; ++j) {
        v[j]     = __ldcs(p0 + tid + j * BT);
        v[j + 5] = __ldcs(p1 + tid + j * BT);
    }

    float s0 = 0.f, s1 = 0.f;
    #pragma unroll
    for (int j = 0; j < 5; ++j) {
        s0 += (v[j].x + v[j].y) + (v[j].z + v[j].w);
        s1 += (v[j + 5].x + v[j + 5].y) + (v[j + 5].z + v[j + 5].w);
    }
    float s = s0 + s1;

    // warp reduce
    #pragma unroll
    for (int off = 16; off > 0; off >>= 1)
        s += __shfl_down_sync(0xFFFFFFFFu, s, off);

    __shared__ float warp_sums[10];
    const int lane = tid & 31;
    const int wid  = tid >> 5;
    if (lane == 0) warp_sums[wid] = s;
    __syncthreads();

    if (wid == 0) {
        float t = (lane < 10) ? warp_sums[lane] : 0.f;
        #pragma unroll
        for (int off = 8; off > 0; off >>= 1)
            t += __shfl_down_sync(0xFFFFFFFFu, t, off);
        if (lane == 0)
            out[bid] = t * 0.05f;   // (1/M) * (1/Kl) = (1/2)*(1/10)
    }
}

extern "C" void kernel_launch(void* const* d_in, const int* in_sizes, int n_in,
                              void* d_out, int out_size) {
    const float* x = (const float*)d_in[0];   // [N, M, C, T, V] fp32
    float* out = (float*)d_out;               // [N, C] fp32
    (void)in_sizes; (void)n_in; (void)out_size;
    pretrain_neck_reduce<<<N_SAMP * C_DIM, BT>>>(x, out);
}